// round 5
// baseline (speedup 1.0000x reference)
#include <cuda_runtime.h>
#include <cstdint>

// YOLO-v1 style loss reduction — TMA bulk-copy double-buffered persistent version.
// prediction: [16384, 7, 7, 30] f32, target: [16384, 7, 7, 25] f32 -> scalar f32.
//
// R4 post-mortem: cp.async per-16B staging was LDGSTS-issue-bound (8 cyc/op/SMSP
// => ~3520 cyc to issue one tile vs ~1.6K cyc of data time). Replace with
// cp.async.bulk (TMA): one instruction per tile per stream, mbarrier
// complete_tx. Persistent grid = 148*4 blocks (one exact wave).

#define TPB        128
#define GRID       592                       // 148 SMs x 4 blocks (smem-limited)
#define NCELLS     (16384 * 49)              // 802816
#define NTILES     (NCELLS / TPB)            // 6272
#define PRED_F     30
#define TARG_F     25
#define PFLT       (TPB * PRED_F)            // 3840 floats
#define TFLT       (TPB * TARG_F)            // 3200 floats
#define PBYTES     (PFLT * 4)                // 15360
#define TBYTES     (TFLT * 4)                // 12800
#define STAGE_BYTES (PBYTES + TBYTES)        // 28160
#define DYN_BYTES  (2 * STAGE_BYTES)         // 56320
#define EPSV       1e-8f

__global__ void zero_out_kernel(float* out) { *out = 0.0f; }

__device__ __forceinline__ void mbar_init(uint32_t mbar, uint32_t count) {
    asm volatile("mbarrier.init.shared.b64 [%0], %1;" :: "r"(mbar), "r"(count) : "memory");
}
__device__ __forceinline__ void mbar_expect_tx(uint32_t mbar, uint32_t bytes) {
    asm volatile("mbarrier.arrive.expect_tx.shared.b64 _, [%0], %1;"
                 :: "r"(mbar), "r"(bytes) : "memory");
}
__device__ __forceinline__ void mbar_wait(uint32_t mbar, uint32_t parity) {
    uint32_t done;
    asm volatile(
        "{\n\t.reg .pred p;\n\t"
        "mbarrier.try_wait.parity.acquire.cta.shared::cta.b64 p, [%1], %2;\n\t"
        "selp.b32 %0, 1, 0, p;\n\t}"
        : "=r"(done) : "r"(mbar), "r"(parity) : "memory");
    if (!done) {
        asm volatile(
            "{\n\t.reg .pred P1;\n\t"
            "WAIT_LOOP_%=:\n\t"
            "mbarrier.try_wait.parity.acquire.cta.shared::cta.b64 P1, [%0], %1, 0x989680;\n\t"
            "@P1 bra.uni WAIT_DONE_%=;\n\t"
            "bra.uni WAIT_LOOP_%=;\n\t"
            "WAIT_DONE_%=:\n\t}"
            :: "r"(mbar), "r"(parity) : "memory");
    }
}
__device__ __forceinline__ void bulk_cp(uint32_t dst_smem, const void* src, uint32_t bytes,
                                        uint32_t mbar) {
    asm volatile(
        "cp.async.bulk.shared::cluster.global.mbarrier::complete_tx::bytes [%0], [%1], %2, [%3];"
        :: "r"(dst_smem), "l"(src), "r"(bytes), "r"(mbar) : "memory");
}

__global__ void __launch_bounds__(TPB)
yolo_loss_kernel(const float* __restrict__ pred,
                 const float* __restrict__ targ,
                 float* __restrict__ out)
{
    extern __shared__ float dyn[];
    // layout per stage: [pred tile | targ tile], two stages.
    float* spbuf[2] = { dyn,                          dyn + (PFLT + TFLT) };
    float* stbuf[2] = { dyn + PFLT,                   dyn + (PFLT + TFLT) + PFLT };
    __shared__ __align__(8) unsigned long long mbar_s[2];
    __shared__ float wsum[TPB / 32];

    const int tid = threadIdx.x;

    uint32_t mb[2];
    mb[0] = (uint32_t)__cvta_generic_to_shared(&mbar_s[0]);
    mb[1] = (uint32_t)__cvta_generic_to_shared(&mbar_s[1]);
    uint32_t spa[2], sta[2];
    spa[0] = (uint32_t)__cvta_generic_to_shared(spbuf[0]);
    spa[1] = (uint32_t)__cvta_generic_to_shared(spbuf[1]);
    sta[0] = (uint32_t)__cvta_generic_to_shared(stbuf[0]);
    sta[1] = (uint32_t)__cvta_generic_to_shared(stbuf[1]);

    if (tid == 0) {
        mbar_init(mb[0], 1);
        mbar_init(mb[1], 1);
    }
    __syncthreads();

    // prologue: prefetch first tile into stage 0
    int tile = blockIdx.x;
    if (tid == 0 && tile < NTILES) {
        mbar_expect_tx(mb[0], STAGE_BYTES);
        bulk_cp(spa[0], pred + (size_t)tile * PFLT, PBYTES, mb[0]);
        bulk_cp(sta[0], targ + (size_t)tile * TFLT, TBYTES, mb[0]);
    }

    float acc = 0.0f;
    const float invS = 1.0f / 7.0f;
    int ph0 = 0, ph1 = 0;

    for (int k = 0; tile < NTILES; tile += GRID, k++) {
        const int buf = k & 1;

        // prefetch next tile into the other stage (its last readers finished
        // before the __syncthreads closing iteration k-1)
        const int nxt = tile + GRID;
        if (tid == 0 && nxt < NTILES) {
            mbar_expect_tx(mb[buf ^ 1], STAGE_BYTES);
            bulk_cp(spa[buf ^ 1], pred + (size_t)nxt * PFLT, PBYTES, mb[buf ^ 1]);
            bulk_cp(sta[buf ^ 1], targ + (size_t)nxt * TFLT, TBYTES, mb[buf ^ 1]);
        }

        // wait for current stage
        if (buf == 0) { mbar_wait(mb[0], ph0); ph0 ^= 1; }
        else          { mbar_wait(mb[1], ph1); ph1 ^= 1; }

        // ---- per-cell loss ----
        const int cell = tile * TPB + tid;
        const int rc   = cell % 49;
        const float row = (float)(rc / 7);
        const float col = (float)(rc % 7);

        const float* p  = spbuf[buf] + tid * PRED_F;
        const float* tt = stbuf[buf] + tid * TARG_F;

        const float gw = tt[2], gh = tt[3];
        const float gcx = (tt[0] + col) * invS;
        const float gcy = (tt[1] + row) * invS;
        const float gx1 = gcx - 0.5f * gw, gy1 = gcy - 0.5f * gh;
        const float gx2 = gcx + 0.5f * gw, gy2 = gcy + 0.5f * gh;
        const float ga  = fabsf(gw * gh);

        float iou0 = 0.0f, iou1 = 0.0f;
        #pragma unroll
        for (int b = 0; b < 2; b++) {
            const float* pb = p + 5 * b;
            const float w = pb[2], h = pb[3];
            const float cx = (pb[0] + col) * invS;
            const float cy = (pb[1] + row) * invS;
            const float x1 = cx - 0.5f * w, y1 = cy - 0.5f * h;
            const float x2 = cx + 0.5f * w, y2 = cy + 0.5f * h;
            const float ix = fminf(x2, gx2) - fmaxf(x1, gx1);
            const float iy = fminf(y2, gy2) - fmaxf(y1, gy1);
            const float inter = fmaxf(ix, 0.0f) * fmaxf(iy, 0.0f);
            const float pa = fabsf(w * h);
            const float v  = inter / (pa + ga - inter + EPSV);
            if (b == 0) iou0 = v; else iou1 = v;
        }
        const int bi = (iou1 > iou0) ? 1 : 0;     // argmax: first max wins
        const float* s = p + 5 * bi;

        const float gc  = tt[4];
        const bool  obj = (gc != 0.0f);

        float loss;
        if (obj) {
            const float dx = s[0] - tt[0];
            const float dy = s[1] - tt[1];
            const float center = dx * dx + dy * dy;

            const float pw = s[2], ph = s[3];
            const float sgnw = (pw > 0.0f) ? 1.0f : ((pw < 0.0f) ? -1.0f : 0.0f);
            const float sgnh = (ph > 0.0f) ? 1.0f : ((ph < 0.0f) ? -1.0f : 0.0f);
            const float swv = sgnw * sqrtf(fabsf(pw) + EPSV) - sqrtf(gw);
            const float shv = sgnh * sqrtf(fabsf(ph) + EPSV) - sqrtf(gh);
            const float dim = swv * swv + shv * shv;

            const float dc = s[4] - gc;
            float cls = 0.0f;
            #pragma unroll
            for (int c = 0; c < 20; c++) {
                const float d = p[10 + c] - tt[5 + c];
                cls += d * d;
            }
            loss = 5.0f * (center + dim) + dc * dc + cls;
        } else {
            const float d0 = p[4] - gc;
            const float d1 = p[9] - gc;
            loss = 0.5f * (d0 * d0 + d1 * d1);
        }
        acc += loss;

        __syncthreads();   // all readers done with buf before it is refilled (k+2)
    }

    // ---- block reduction ----
    #pragma unroll
    for (int o = 16; o > 0; o >>= 1)
        acc += __shfl_down_sync(0xffffffffu, acc, o);
    if ((tid & 31) == 0) wsum[tid >> 5] = acc;
    __syncthreads();
    if (tid < (TPB / 32)) {
        float v = wsum[tid];
        #pragma unroll
        for (int o = (TPB / 64); o > 0; o >>= 1)
            v += __shfl_down_sync(0x0000000fu, v, o);
        if (tid == 0) atomicAdd(out, v);
    }
}

extern "C" void kernel_launch(void* const* d_in, const int* in_sizes, int n_in,
                              void* d_out, int out_size)
{
    const float* pred = (const float*)d_in[0];
    const float* targ = (const float*)d_in[1];
    float* out = (float*)d_out;

    cudaFuncSetAttribute(yolo_loss_kernel,
                         cudaFuncAttributeMaxDynamicSharedMemorySize,
                         DYN_BYTES);

    zero_out_kernel<<<1, 1>>>(out);
    yolo_loss_kernel<<<GRID, TPB, DYN_BYTES>>>(pred, targ, out);
}